// round 11
// baseline (speedup 1.0000x reference)
#include <cuda_runtime.h>
#include <cuda_bf16.h>
#include <stdint.h>

#define BB 32
#define SS 8192
#define DD 512
#define MM 16
#define CHUNKS 64
#define CSZ (SS/CHUNKS)      /* 128 */
#define TS 16
#define NT (CSZ/TS)          /* 8 */
#define NTHREADS 256

/* per-CTA smem byte offsets */
#define OXH 0u               /* xh[16][512] bf16 swizzled = 16384 B (also seed-hi staging in prologue) */
#define OXL 16384u           /* xl likewise */
#define OXF 32768u           /* fp32 cp.async staging [16][512] = 32768 B */
#define ORED 65536u          /* fp32 [8][16][17] = 8704 B */
#define OPTH 74240u          /* P^T hi [16][48B] */
#define OPTL 75008u
#define OLRED 75776u         /* float[256] */
#define OLINV 76800u         /* float[16] */
#define OFLAG 76864u
#define SMEMSZ 76928u

__device__ float g_partA[BB*CHUNKS*MM*DD];
__device__ float g_partL[BB*CHUNKS*MM];
__device__ unsigned g_cnt[BB];

__device__ __forceinline__ unsigned sptr(const void* p) {
    return (unsigned)__cvta_generic_to_shared(p);
}
__device__ __forceinline__ void ldm_x4(unsigned* r, unsigned a) {
    asm volatile("ldmatrix.sync.aligned.m8n8.x4.shared.b16 {%0,%1,%2,%3}, [%4];"
                 : "=r"(r[0]), "=r"(r[1]), "=r"(r[2]), "=r"(r[3]) : "r"(a));
}
__device__ __forceinline__ void ldm_x2(unsigned* r, unsigned a) {
    asm volatile("ldmatrix.sync.aligned.m8n8.x2.shared.b16 {%0,%1}, [%2];"
                 : "=r"(r[0]), "=r"(r[1]) : "r"(a));
}
__device__ __forceinline__ void ldm_x2t(unsigned* r, unsigned a) {
    asm volatile("ldmatrix.sync.aligned.m8n8.x2.trans.shared.b16 {%0,%1}, [%2];"
                 : "=r"(r[0]), "=r"(r[1]) : "r"(a));
}
__device__ __forceinline__ void mma(float* c, const unsigned* a, const unsigned* b) {
    asm volatile("mma.sync.aligned.m16n8k16.row.col.f32.bf16.bf16.f32 "
                 "{%0,%1,%2,%3}, {%4,%5,%6,%7}, {%8,%9}, {%0,%1,%2,%3};"
                 : "+f"(c[0]), "+f"(c[1]), "+f"(c[2]), "+f"(c[3])
                 : "r"(a[0]), "r"(a[1]), "r"(a[2]), "r"(a[3]), "r"(b[0]), "r"(b[1]));
}
__device__ __forceinline__ void splitf4(float4 v, uint2& h, uint2& l) {
    __nv_bfloat162 h01 = __float22bfloat162_rn(make_float2(v.x, v.y));
    __nv_bfloat162 h23 = __float22bfloat162_rn(make_float2(v.z, v.w));
    float2 r01 = make_float2(v.x - __bfloat162float(h01.x), v.y - __bfloat162float(h01.y));
    float2 r23 = make_float2(v.z - __bfloat162float(h23.x), v.w - __bfloat162float(h23.y));
    __nv_bfloat162 l01 = __float22bfloat162_rn(r01);
    __nv_bfloat162 l23 = __float22bfloat162_rn(r23);
    h.x = *(unsigned*)&h01; h.y = *(unsigned*)&h23;
    l.x = *(unsigned*)&l01; l.y = *(unsigned*)&l23;
}
__device__ __forceinline__ void cpasync16(unsigned sdst, const void* gsrc) {
    asm volatile("cp.async.cg.shared.global [%0], [%1], 16;\n" :: "r"(sdst), "l"(gsrc));
}

__global__ void __launch_bounds__(NTHREADS, 2)
attn_pool_mma(const float* __restrict__ x, const float* __restrict__ seeds,
              float* __restrict__ out) {
    extern __shared__ char smc[];
    const unsigned sb = sptr(smc);
    float* redp = (float*)(smc + ORED);
    float* lred = (float*)(smc + OLRED);
    float* linv = (float*)(smc + OLINV);
    unsigned* flag = (unsigned*)(smc + OFLAG);

    const int t = threadIdx.x, w = t >> 5, l = t & 31;
    const int chunk = blockIdx.x, b = blockIdx.y;
    const int lrow = (l & 7) + ((l >> 3) & 1) * 8;  /* ldm x4 A-tile row */
    const int lsel = l >> 4;                        /* x4 k-granule select */
    const int qr = l >> 2, qc = (l & 3) * 2;        /* c-frag (row,col) base */

    const float4* xb4 = (const float4*)(x + ((size_t)b * SS + (size_t)chunk * CSZ) * DD);

    /* ---- prologue ---- */
    /* tile 0 -> fp32 staging (async), overlapped with seed prep */
#pragma unroll
    for (int i = 0; i < 8; i++) {
        int idx = t + i * NTHREADS;
        cpasync16(sb + OXF + idx * 16, &xb4[idx]);
    }
    asm volatile("cp.async.commit_group;\n" ::: "memory");

    /* seeds: LDG -> split -> swizzled STS into OXH/OXL (staging; same layout as x tiles) */
#pragma unroll
    for (int i = 0; i < 8; i++) {
        int idx = t + i * NTHREADS, r = idx >> 7, c4 = idx & 127;
        float4 v = ((const float4*)seeds)[idx];
        uint2 h, lo;
        splitf4(v, h, lo);
        unsigned off = r * 1024 + ((((unsigned)c4 >> 1) ^ (r & 7)) << 4) + (c4 & 1) * 8;
        *(uint2*)(smc + OXH + off) = h;
        *(uint2*)(smc + OXL + off) = lo;
    }
    __syncthreads();

    /* seed B-fragments, register-resident: warp k-slice [64w, 64w+64) */
    unsigned sbh[4][2][2], sbl[4][2][2];
#pragma unroll
    for (int ks = 0; ks < 4; ks++)
#pragma unroll
        for (int nb = 0; nb < 2; nb++) {
            int row = nb * 8 + (l & 7);
            int klf = (l >> 3) & 1;
            unsigned gr = (unsigned)((8 * w + 2 * ks + klf) ^ (row & 7));
            ldm_x2(sbh[ks][nb], sb + OXH + row * 1024 + (gr << 4));
            ldm_x2(sbl[ks][nb], sb + OXL + row * 1024 + (gr << 4));
        }
    __syncthreads();   /* frags in regs; OXH/OXL reusable */

    /* convert tile 0: staging -> swizzled bf16 hi/lo */
    asm volatile("cp.async.wait_group 0;\n" ::: "memory");
    __syncthreads();
#pragma unroll
    for (int i = 0; i < 8; i++) {
        int idx = t + i * NTHREADS, r = idx >> 7, c4 = idx & 127;
        float4 v = *(const float4*)(smc + OXF + idx * 16);
        uint2 h, lo;
        splitf4(v, h, lo);
        unsigned off = r * 1024 + ((((unsigned)c4 >> 1) ^ (r & 7)) << 4) + (c4 & 1) * 8;
        *(uint2*)(smc + OXH + off) = h;
        *(uint2*)(smc + OXL + off) = lo;
    }
    /* issue tile 1 -> staging */
    if (1 < NT) {
#pragma unroll
        for (int i = 0; i < 8; i++) {
            int idx = t + i * NTHREADS;
            cpasync16(sb + OXF + idx * 16, &xb4[(size_t)TS * 128 + idx]);
        }
        asm volatile("cp.async.commit_group;\n" ::: "memory");
    }
    __syncthreads();

    float acc[8][4];
#pragma unroll
    for (int i = 0; i < 8; i++)
#pragma unroll
        for (int j = 0; j < 4; j++) acc[i][j] = 0.f;
    float lsum = 0.f;

    for (int tl = 0; tl < NT; ++tl) {
        /* ---- phase 1: scores, warp k-slice [64w,64w+64), s rows 0..15 ---- */
        {
            float c[2][4];
#pragma unroll
            for (int nb = 0; nb < 2; nb++)
#pragma unroll
                for (int j = 0; j < 4; j++) c[nb][j] = 0.f;
#pragma unroll
            for (int ks = 0; ks < 4; ks++) {
                int s = lrow;
                unsigned gr = (unsigned)((8 * w + 2 * ks + lsel) ^ (s & 7));
                unsigned ah[4], al[4];
                ldm_x4(ah, sb + OXH + s * 1024 + (gr << 4));
                ldm_x4(al, sb + OXL + s * 1024 + (gr << 4));
                mma(c[0], ah, sbh[ks][0]);
                mma(c[0], ah, sbl[ks][0]);
                mma(c[0], al, sbh[ks][0]);
                mma(c[1], ah, sbh[ks][1]);
                mma(c[1], ah, sbl[ks][1]);
                mma(c[1], al, sbh[ks][1]);
            }
#pragma unroll
            for (int nb = 0; nb < 2; nb++) {
                int i0 = w * 272 + qr * 17 + nb * 8 + qc;
                redp[i0] = c[nb][0];
                redp[i0 + 1] = c[nb][1];
                redp[i0 + 8 * 17] = c[nb][2];
                redp[i0 + 8 * 17 + 1] = c[nb][3];
            }
        }
        __syncthreads();

        /* ---- reduce over 8 warps, exp, P^T hi/lo (thread <-> (s,m) 1:1) ---- */
        {
            int s0 = t >> 4, m0 = t & 15;
            float a0 = 0.f;
#pragma unroll
            for (int ww = 0; ww < 8; ww++)
                a0 += redp[ww * 272 + s0 * 17 + m0];
            float e0 = __expf(a0);   /* scores bounded: no max-subtraction needed */
            lsum += e0;
            __nv_bfloat16 h0 = __float2bfloat16(e0);
            __nv_bfloat16 o0 = __float2bfloat16(e0 - __bfloat162float(h0));
            *(__nv_bfloat16*)(smc + OPTH + m0 * 48 + s0 * 2) = h0;
            *(__nv_bfloat16*)(smc + OPTL + m0 * 48 + s0 * 2) = o0;
        }
        __syncthreads();

        /* ---- phase 2: acc[16m, 64d slice] += P^T @ X (k = 16 s-rows) ---- */
        {
            unsigned pah[4], pal[4];
            unsigned ad = (unsigned)(lrow * 48 + lsel * 16);
            ldm_x4(pah, sb + OPTH + ad);
            ldm_x4(pal, sb + OPTL + ad);
            int sx = l & 15;
#pragma unroll
            for (int nt = 0; nt < 8; nt++) {
                int gn = 8 * w + nt;
                unsigned ga = sb + OXH + sx * 1024 + ((unsigned)(gn ^ (sx & 7)) << 4);
                unsigned bh[2], bl[2];
                ldm_x2t(bh, ga);
                ldm_x2t(bl, ga + 16384u);
                mma(acc[nt], pah, bh);
                mma(acc[nt], pah, bl);
                mma(acc[nt], pal, bh);
            }
        }
        __syncthreads();   /* xh/xl free */

        /* ---- convert next tile from staging; issue tile tl+2 ---- */
        if (tl + 1 < NT) {
            asm volatile("cp.async.wait_group 0;\n" ::: "memory");
            /* per-thread wait; visibility via trailing barrier (each thread converts
               exactly the bytes it copied, so no cross-thread read before barrier) */
#pragma unroll
            for (int i = 0; i < 8; i++) {
                int idx = t + i * NTHREADS, r = idx >> 7, c4 = idx & 127;
                float4 v = *(const float4*)(smc + OXF + idx * 16);
                uint2 h, lo;
                splitf4(v, h, lo);
                unsigned off = r * 1024 + ((((unsigned)c4 >> 1) ^ (r & 7)) << 4) + (c4 & 1) * 8;
                *(uint2*)(smc + OXH + off) = h;
                *(uint2*)(smc + OXL + off) = lo;
            }
            if (tl + 2 < NT) {
#pragma unroll
                for (int i = 0; i < 8; i++) {
                    int idx = t + i * NTHREADS;
                    cpasync16(sb + OXF + idx * 16,
                              &xb4[(size_t)(tl + 2) * TS * 128 + idx]);
                }
                asm volatile("cp.async.commit_group;\n" ::: "memory");
            }
        }
        __syncthreads();
    }

    /* ---- per-chunk partials ---- */
    {
        size_t base = ((size_t)(b * CHUNKS + chunk) * MM) * DD;
#pragma unroll
        for (int nt = 0; nt < 8; nt++) {
            int d0 = w * 64 + nt * 8 + qc;
            *(float2*)&g_partA[base + (size_t)qr * DD + d0] =
                make_float2(acc[nt][0], acc[nt][1]);
            *(float2*)&g_partA[base + (size_t)(qr + 8) * DD + d0] =
                make_float2(acc[nt][2], acc[nt][3]);
        }
        lred[t] = lsum;
    }
    __syncthreads();
    if (t < MM) {
        float tot = 0.f;
#pragma unroll
        for (int i = 0; i < NTHREADS; i += MM) tot += lred[i + t];
        g_partL[(b * CHUNKS + chunk) * MM + t] = tot;
    }

    /* ---- last-CTA-per-batch fused merge ---- */
    __threadfence();
    __syncthreads();
    if (t == 0) {
        unsigned old = atomicAdd(&g_cnt[b], 1u);
        flag[0] = ((old & (CHUNKS - 1)) == (CHUNKS - 1)) ? 1u : 0u;
    }
    __syncthreads();
    if (flag[0]) {
        __threadfence();
        if (t < MM) {
            float sl = 0.f;
#pragma unroll
            for (int c2i = 0; c2i < CHUNKS; c2i++)
                sl += g_partL[(b * CHUNKS + c2i) * MM + t];
            linv[t] = 1.f / sl;
        }
        __syncthreads();
        float4* ob = (float4*)(out + (size_t)b * MM * DD);
#pragma unroll
        for (int i = 0; i < 8; i++) {
            int o = t + i * NTHREADS;
            int m = o >> 7, d4 = o & 127;
            float4 a = make_float4(0.f, 0.f, 0.f, 0.f);
#pragma unroll 8
            for (int c2i = 0; c2i < CHUNKS; c2i++) {
                const float4* pa =
                    (const float4*)&g_partA[(((size_t)(b * CHUNKS + c2i)) * MM + m) * DD];
                float4 v = pa[d4];
                a.x += v.x; a.y += v.y; a.z += v.z; a.w += v.w;
            }
            float inv = linv[m];
            ob[o] = make_float4(a.x * inv, a.y * inv, a.z * inv, a.w * inv);
        }
    }
}

extern "C" void kernel_launch(void* const* d_in, const int* in_sizes, int n_in,
                              void* d_out, int out_size) {
    const float* x = (const float*)d_in[0];
    const float* seeds = (const float*)d_in[1];
    float* out = (float*)d_out;

    cudaFuncSetAttribute(attn_pool_mma,
                         cudaFuncAttributeMaxDynamicSharedMemorySize, (int)SMEMSZ);
    dim3 grid(CHUNKS, BB);
    attn_pool_mma<<<grid, NTHREADS, SMEMSZ>>>(x, seeds, out);
}